// round 3
// baseline (speedup 1.0000x reference)
#include <cuda_runtime.h>
#include <cstdint>

#define BATCH 64
#define T 512
#define C 384
#define H 64
#define BT (BATCH*T)

// Q: A-fragment layout per 16-row group: grp*1024 + (g*4+tg)*32 + ks*4 + slot
//    slot = rhalf + 2*khalf;  element Q[grp*16 + g + 8*rhalf][8*ks + tg + 4*khalf]
// K: row-major rows, columns permuted: row*64 + ks*8 + tg*2 + e  <-> K[row][8ks+tg+4e]
// V: transposed per 64-row tile: tile*64 + h*64 + ks*8 + tg*2 + e <-> V[tile+8ks+tg+4e][h]
__device__ uint32_t g_Q[BT * H];
__device__ uint32_t g_K[BT * H];
__device__ uint32_t g_V[BT * H];

__device__ __forceinline__ uint32_t f2tf32(float f) {
    uint32_t r;
    asm("cvt.rna.tf32.f32 %0, %1;" : "=r"(r) : "f"(f));
    return r;
}

__device__ __forceinline__ void mma_tf32(float c[4], const uint32_t a[4],
                                         uint32_t b0, uint32_t b1) {
    asm volatile(
        "mma.sync.aligned.m16n8k8.row.col.f32.tf32.tf32.f32 "
        "{%0,%1,%2,%3}, {%4,%5,%6,%7}, {%8,%9}, {%0,%1,%2,%3};\n"
        : "+f"(c[0]), "+f"(c[1]), "+f"(c[2]), "+f"(c[3])
        : "r"(a[0]), "r"(a[1]), "r"(a[2]), "r"(a[3]), "r"(b0), "r"(b1));
}

// ---------------------------------------------------------------------------
// Kernel 1: fused QKV projection — one x read feeds all three GEMMs.
// Grid BT/128 = 256 blocks, 384 threads = 12 warps: warpM = wid&3 (32 rows),
// mat = wid>>2 (0=Q,1=K,2=V). Outputs written in attn fragment layouts.
// ---------------------------------------------------------------------------
__global__ __launch_bounds__(384) void qkv_proj_kernel(
    const float* __restrict__ x,
    const float* __restrict__ Wq,
    const float* __restrict__ Wk,
    const float* __restrict__ Wv)
{
    __shared__ uint32_t As[128][36];      // x tile (tf32) [m][k]
    __shared__ uint32_t Bs[3][32][72];    // weight tiles  [mat][k][n]

    const int tid  = threadIdx.x;
    const int lane = tid & 31;
    const int wid  = tid >> 5;
    const int warpM = wid & 3;
    const int mat   = wid >> 2;
    const int g  = lane >> 2;
    const int tg = lane & 3;
    const int row0 = blockIdx.x * 128;

    float c[2][8][4];
    #pragma unroll
    for (int mf = 0; mf < 2; ++mf)
        #pragma unroll
        for (int nf = 0; nf < 8; ++nf)
            #pragma unroll
            for (int j = 0; j < 4; ++j) c[mf][nf][j] = 0.0f;

    for (int kt = 0; kt < C / 32; ++kt) {
        // x tile 128x32
        for (int idx = tid; idx < 128 * 32; idx += 384) {
            int r = idx >> 5, kk = idx & 31;
            As[r][kk] = f2tf32(x[(row0 + r) * C + kt * 32 + kk]);
        }
        // weight tiles 3 x 32x64
        for (int idx = tid; idx < 3 * 32 * 64; idx += 384) {
            int w = idx >> 11;
            int rem = idx & 2047;
            int k = rem >> 6, n = rem & 63;
            const float* Wp = (w == 0) ? Wq : ((w == 1) ? Wk : Wv);
            Bs[w][k][n] = f2tf32(Wp[(kt * 32 + k) * H + n]);
        }
        __syncthreads();

        #pragma unroll
        for (int ks = 0; ks < 4; ++ks) {
            uint32_t a[2][4];
            const int k = ks * 8 + tg;
            #pragma unroll
            for (int mf = 0; mf < 2; ++mf) {
                int r = warpM * 32 + mf * 16 + g;
                a[mf][0] = As[r][k];
                a[mf][1] = As[r + 8][k];
                a[mf][2] = As[r][k + 4];
                a[mf][3] = As[r + 8][k + 4];
            }
            #pragma unroll
            for (int nf = 0; nf < 8; ++nf) {
                int n = nf * 8 + g;
                uint32_t b0 = Bs[mat][k][n];
                uint32_t b1 = Bs[mat][k + 4][n];
                #pragma unroll
                for (int mf = 0; mf < 2; ++mf)
                    mma_tf32(c[mf][nf], a[mf], b0, b1);
            }
        }
        __syncthreads();
    }

    // Epilogue: scatter into the attn-native layouts (scalar stores; L2 merges).
    #pragma unroll
    for (int mf = 0; mf < 2; ++mf)
        #pragma unroll
        for (int nf = 0; nf < 8; ++nf)
            #pragma unroll
            for (int j = 0; j < 4; ++j) {
                int row = row0 + warpM * 32 + mf * 16 + g + 8 * (j >> 1);
                int col = nf * 8 + 2 * tg + (j & 1);
                uint32_t v = f2tf32(c[mf][nf][j]);
                if (mat == 0) {
                    int grp = row >> 4;
                    int lane_c = (row & 7) * 4 + (col & 3);
                    int slot = ((row >> 3) & 1) + 2 * ((col >> 2) & 1);
                    g_Q[grp * 1024 + lane_c * 32 + (col >> 3) * 4 + slot] = v;
                } else if (mat == 1) {
                    g_K[row * 64 + (col >> 3) * 8 + (col & 3) * 2 + ((col >> 2) & 1)] = v;
                } else {
                    int tile = row & ~63, rw = row & 63;
                    g_V[tile * 64 + col * 64 + (rw >> 3) * 8 + (rw & 3) * 2 + ((rw >> 2) & 1)] = v;
                }
            }
}

// ---------------------------------------------------------------------------
// Kernel 2: causal flash attention, fragment-vectorized.
// Grid (8, 64) with qt reversed (heavy tiles first). 128 threads = 4 warps.
// ---------------------------------------------------------------------------
#define KV_STR 72                         // words per K/V smem row (64 data + 8 pad)
#define P_WARP 1152                       // words per warp P region (32 lanes * 36)
#define ATTN_SMEM_WORDS (2 * 64 * KV_STR + 4 * P_WARP)
#define ATTN_SMEM_BYTES (ATTN_SMEM_WORDS * 4)

__global__ __launch_bounds__(128) void attn_kernel(float* __restrict__ out)
{
    extern __shared__ uint32_t sm[];
    uint32_t* Ks = sm;                     // [64][72]
    uint32_t* Vs = Ks + 64 * KV_STR;       // [64][72]
    uint32_t* Ps = Vs + 64 * KV_STR;       // [4][1152]

    const int tid  = threadIdx.x;
    const int lane = tid & 31;
    const int wid  = tid >> 5;
    const int g    = lane >> 2;
    const int tg   = lane & 3;
    const int qt = (T / 64 - 1) - blockIdx.x;   // heavy first
    const int b  = blockIdx.y;
    const float scale = 0.125f;

    // Q fragments straight from gmem (A-fragment layout): 8 x uint4.
    uint32_t qa[8][4];
    {
        const int qoff = (((b * T + qt * 64) >> 4) + wid) * 1024 + lane * 32;
        #pragma unroll
        for (int ks = 0; ks < 8; ++ks) {
            uint4 v = *(const uint4*)&g_Q[qoff + ks * 4];
            qa[ks][0] = v.x; qa[ks][1] = v.y; qa[ks][2] = v.z; qa[ks][3] = v.w;
        }
    }

    float m[2] = {-1e30f, -1e30f};
    float l[2] = {0.0f, 0.0f};
    float o[8][4];
    #pragma unroll
    for (int nf = 0; nf < 8; ++nf)
        #pragma unroll
        for (int j = 0; j < 4; ++j) o[nf][j] = 0.0f;

    // P addressing (constant per thread)
    const int col0 = 2 * tg, col1 = 2 * tg + 1;
    const int pa0 = wid * P_WARP + (g * 4 + (col0 & 3)) * 36 + 2 * ((col0 >> 2) & 1);
    const int pa1 = wid * P_WARP + (g * 4 + (col1 & 3)) * 36 + 2 * ((col1 >> 2) & 1);
    const int prd = wid * P_WARP + lane * 36;

    for (int t = 0; t <= qt; ++t) {
        __syncthreads();
        const int koff = (b * T + t * 64) * 64;
        #pragma unroll
        for (int i = 0; i < 8; ++i) {
            int s = tid + i * 128;
            int r = s >> 4, c4 = (s & 15) * 4;
            *(uint4*)&Ks[r * KV_STR + c4] = *(const uint4*)&g_K[koff + r * 64 + c4];
            *(uint4*)&Vs[r * KV_STR + c4] = *(const uint4*)&g_V[koff + r * 64 + c4];
        }
        __syncthreads();

        // --- S = Q K^T ---
        float sf[8][4];
        #pragma unroll
        for (int nf = 0; nf < 8; ++nf)
            #pragma unroll
            for (int j = 0; j < 4; ++j) sf[nf][j] = 0.0f;

        #pragma unroll
        for (int ks = 0; ks < 8; ++ks) {
            const int kw = ks * 8 + tg * 2;
            #pragma unroll
            for (int nf = 0; nf < 8; ++nf) {
                uint2 bk = *(const uint2*)&Ks[(nf * 8 + g) * KV_STR + kw];
                mma_tf32(sf[nf], qa[ks], bk.x, bk.y);
            }
        }

        // --- online softmax ---
        const bool last = (t == qt);
        float mnew[2] = {m[0], m[1]};
        #pragma unroll
        for (int nf = 0; nf < 8; ++nf)
            #pragma unroll
            for (int j = 0; j < 4; ++j) {
                int rr = j >> 1;
                float v = sf[nf][j] * scale;
                if (last) {
                    int col = nf * 8 + 2 * tg + (j & 1);
                    int row = wid * 16 + g + rr * 8;
                    if (col > row) v = -1e30f;
                }
                sf[nf][j] = v;
                mnew[rr] = fmaxf(mnew[rr], v);
            }
        #pragma unroll
        for (int rr = 0; rr < 2; ++rr) {
            mnew[rr] = fmaxf(mnew[rr], __shfl_xor_sync(0xffffffffu, mnew[rr], 1));
            mnew[rr] = fmaxf(mnew[rr], __shfl_xor_sync(0xffffffffu, mnew[rr], 2));
        }
        float alpha[2];
        #pragma unroll
        for (int rr = 0; rr < 2; ++rr) {
            alpha[rr] = __expf(m[rr] - mnew[rr]);
            m[rr] = mnew[rr];
        }
        float ls[2] = {0.0f, 0.0f};
        #pragma unroll
        for (int nf = 0; nf < 8; ++nf)
            #pragma unroll
            for (int j = 0; j < 4; ++j) {
                int rr = j >> 1;
                float p = __expf(sf[nf][j] - m[rr]);
                sf[nf][j] = p;
                ls[rr] += p;
            }
        #pragma unroll
        for (int rr = 0; rr < 2; ++rr) {
            ls[rr] += __shfl_xor_sync(0xffffffffu, ls[rr], 1);
            ls[rr] += __shfl_xor_sync(0xffffffffu, ls[rr], 2);
            l[rr] = l[rr] * alpha[rr] + ls[rr];
        }
        #pragma unroll
        for (int nf = 0; nf < 8; ++nf) {
            o[nf][0] *= alpha[0];
            o[nf][1] *= alpha[0];
            o[nf][2] *= alpha[1];
            o[nf][3] *= alpha[1];
        }

        // --- P to smem in PV A-fragment order (uint2 pairs) ---
        #pragma unroll
        for (int nf = 0; nf < 8; ++nf) {
            *(uint2*)&Ps[pa0 + nf * 4] =
                make_uint2(f2tf32(sf[nf][0]), f2tf32(sf[nf][2]));
            *(uint2*)&Ps[pa1 + nf * 4] =
                make_uint2(f2tf32(sf[nf][1]), f2tf32(sf[nf][3]));
        }
        __syncwarp();

        // --- O += P V ---
        #pragma unroll
        for (int ks = 0; ks < 8; ++ks) {
            uint4 pv = *(const uint4*)&Ps[prd + ks * 4];
            uint32_t pa[4] = {pv.x, pv.y, pv.z, pv.w};
            const int kw = ks * 8 + tg * 2;
            #pragma unroll
            for (int nf = 0; nf < 8; ++nf) {
                uint2 bv = *(const uint2*)&Vs[(nf * 8 + g) * KV_STR + kw];
                mma_tf32(o[nf], pa, bv.x, bv.y);
            }
        }
    }

    // epilogue
    const float inv0 = 1.0f / l[0];
    const float inv1 = 1.0f / l[1];
    const int grow = b * T + qt * 64 + wid * 16 + g;
    #pragma unroll
    for (int nf = 0; nf < 8; ++nf) {
        int col = nf * 8 + 2 * tg;
        *(float2*)&out[grow * H + col] =
            make_float2(o[nf][0] * inv0, o[nf][1] * inv0);
        *(float2*)&out[(grow + 8) * H + col] =
            make_float2(o[nf][2] * inv1, o[nf][3] * inv1);
    }
}

// ---------------------------------------------------------------------------
extern "C" void kernel_launch(void* const* d_in, const int* in_sizes, int n_in,
                              void* d_out, int out_size)
{
    const float* x  = (const float*)d_in[0];
    const float* Wq = (const float*)d_in[1];
    const float* Wk = (const float*)d_in[2];
    const float* Wv = (const float*)d_in[3];
    float* out = (float*)d_out;

    qkv_proj_kernel<<<BT / 128, 384>>>(x, Wq, Wk, Wv);

    cudaFuncSetAttribute(attn_kernel,
                         cudaFuncAttributeMaxDynamicSharedMemorySize,
                         ATTN_SMEM_BYTES);
    attn_kernel<<<dim3(T / 64, BATCH), 128, ATTN_SMEM_BYTES>>>(out);
}

// round 4
// speedup vs baseline: 2.0507x; 2.0507x over previous
#include <cuda_runtime.h>
#include <cstdint>

#define BATCH 64
#define T 512
#define C 384
#define H 64
#define BT (BATCH*T)

// Projected Q,K,V as tf32 bit patterns, plain row-major [row*H + col].
__device__ uint32_t g_Q[BT * H];
__device__ uint32_t g_K[BT * H];
__device__ uint32_t g_V[BT * H];

__device__ __forceinline__ uint32_t f2tf32(float f) {
    uint32_t r;
    asm("cvt.rna.tf32.f32 %0, %1;" : "=r"(r) : "f"(f));
    return r;
}

__device__ __forceinline__ void mma_tf32(float c[4], const uint32_t a[4],
                                         uint32_t b0, uint32_t b1) {
    asm volatile(
        "mma.sync.aligned.m16n8k8.row.col.f32.tf32.tf32.f32 "
        "{%0,%1,%2,%3}, {%4,%5,%6,%7}, {%8,%9}, {%0,%1,%2,%3};\n"
        : "+f"(c[0]), "+f"(c[1]), "+f"(c[2]), "+f"(c[3])
        : "r"(a[0]), "r"(a[1]), "r"(a[2]), "r"(a[3]), "r"(b0), "r"(b1));
}

// ---------------------------------------------------------------------------
// Kernel 1: fused QKV projection — one x read feeds all three GEMMs.
// Grid BT/128 = 256 blocks. 384 threads = 12 warps: warpM = wid&3 (32 rows),
// mat = wid>>2 (0=Q,1=K,2=V). Warp computes 32x64 for its matrix.
// Outputs row-major (coalesced uint2 stores), identical layout to round 2.
// ---------------------------------------------------------------------------
__global__ __launch_bounds__(384) void qkv_proj_kernel(
    const float* __restrict__ x,
    const float* __restrict__ Wq,
    const float* __restrict__ Wk,
    const float* __restrict__ Wv)
{
    __shared__ uint32_t As[128][36];      // x tile (tf32) [m][k], A-frag conflict-free
    __shared__ uint32_t Bs[3][32][72];    // weight tiles  [mat][k][n], B-frag conflict-free

    const int tid  = threadIdx.x;
    const int lane = tid & 31;
    const int wid  = tid >> 5;
    const int warpM = wid & 3;
    const int mat   = wid >> 2;
    const int g  = lane >> 2;
    const int tg = lane & 3;
    const int row0 = blockIdx.x * 128;

    float c[2][8][4];
    #pragma unroll
    for (int mf = 0; mf < 2; ++mf)
        #pragma unroll
        for (int nf = 0; nf < 8; ++nf)
            #pragma unroll
            for (int j = 0; j < 4; ++j) c[mf][nf][j] = 0.0f;

    for (int kt = 0; kt < C / 32; ++kt) {
        // x tile 128x32: 4096 floats, vectorized float4 (1024 slots, 384 thr)
        for (int s = tid; s < 128 * 8; s += 384) {
            int r = s >> 3;
            int c4 = (s & 7) * 4;
            float4 v = *(const float4*)&x[(row0 + r) * C + kt * 32 + c4];
            As[r][c4 + 0] = f2tf32(v.x);
            As[r][c4 + 1] = f2tf32(v.y);
            As[r][c4 + 2] = f2tf32(v.z);
            As[r][c4 + 3] = f2tf32(v.w);
        }
        // weight tiles 3 x 32x64: 1536 float4 slots
        for (int s = tid; s < 3 * 32 * 16; s += 384) {
            int w = s >> 9;
            int rem = s & 511;
            int k = rem >> 4;
            int c4 = (rem & 15) * 4;
            const float* Wp = (w == 0) ? Wq : ((w == 1) ? Wk : Wv);
            float4 v = *(const float4*)&Wp[(kt * 32 + k) * H + c4];
            Bs[w][k][c4 + 0] = f2tf32(v.x);
            Bs[w][k][c4 + 1] = f2tf32(v.y);
            Bs[w][k][c4 + 2] = f2tf32(v.z);
            Bs[w][k][c4 + 3] = f2tf32(v.w);
        }
        __syncthreads();

        #pragma unroll
        for (int ks = 0; ks < 4; ++ks) {
            const int k = ks * 8 + tg;
            uint32_t a[2][4];
            #pragma unroll
            for (int mf = 0; mf < 2; ++mf) {
                int r = warpM * 32 + mf * 16 + g;
                a[mf][0] = As[r][k];
                a[mf][1] = As[r + 8][k];
                a[mf][2] = As[r][k + 4];
                a[mf][3] = As[r + 8][k + 4];
            }
            #pragma unroll
            for (int nf = 0; nf < 8; ++nf) {
                int n = nf * 8 + g;
                uint32_t b0 = Bs[mat][k][n];
                uint32_t b1 = Bs[mat][k + 4][n];
                #pragma unroll
                for (int mf = 0; mf < 2; ++mf)
                    mma_tf32(c[mf][nf], a[mf], b0, b1);
            }
        }
        __syncthreads();
    }

    uint32_t* O = (mat == 0) ? g_Q : ((mat == 1) ? g_K : g_V);
    #pragma unroll
    for (int mf = 0; mf < 2; ++mf) {
        int r = row0 + warpM * 32 + mf * 16 + g;
        #pragma unroll
        for (int nf = 0; nf < 8; ++nf) {
            int col = nf * 8 + 2 * tg;
            *(uint2*)&O[r * H + col] =
                make_uint2(f2tf32(c[mf][nf][0]), f2tf32(c[mf][nf][1]));
            *(uint2*)&O[(r + 8) * H + col] =
                make_uint2(f2tf32(c[mf][nf][2]), f2tf32(c[mf][nf][3]));
        }
    }
}

// ---------------------------------------------------------------------------
// Kernel 2: causal flash attention with TF32 mma (round-2 version, verbatim).
// Grid (T/64, BATCH), 128 threads = 4 warps; warp owns 16 q-rows x 64 cols.
// ---------------------------------------------------------------------------
#define QS_STR 68
#define KS_STR 68
#define VS_STR 72
#define PS_STR 68
#define ATTN_SMEM_U32 (64 * (QS_STR + KS_STR + VS_STR + PS_STR))
#define ATTN_SMEM_BYTES (ATTN_SMEM_U32 * 4)

__global__ __launch_bounds__(128) void attn_kernel(float* __restrict__ out)
{
    extern __shared__ uint32_t sm[];
    uint32_t* Qs = sm;
    uint32_t* Ks = Qs + 64 * QS_STR;
    uint32_t* Vs = Ks + 64 * KS_STR;
    uint32_t* Ps = Vs + 64 * VS_STR;

    const int tid  = threadIdx.x;
    const int lane = tid & 31;
    const int wid  = tid >> 5;
    const int g    = lane >> 2;
    const int tg   = lane & 3;
    const int qt = blockIdx.x;
    const int b  = blockIdx.y;
    const float scale = 0.125f;

    const int qoff = (b * T + qt * 64) * H;
    #pragma unroll
    for (int i = 0; i < 8; ++i) {
        int s = tid + i * 128;
        int r = s >> 4;
        int c4 = (s & 15) * 4;
        uint4 v = *(const uint4*)&g_Q[qoff + r * H + c4];
        Qs[r * QS_STR + c4 + 0] = v.x;
        Qs[r * QS_STR + c4 + 1] = v.y;
        Qs[r * QS_STR + c4 + 2] = v.z;
        Qs[r * QS_STR + c4 + 3] = v.w;
    }
    __syncthreads();

    uint32_t qa[8][4];
    const int qrow = wid * 16 + g;
    #pragma unroll
    for (int ks = 0; ks < 8; ++ks) {
        int k = ks * 8 + tg;
        qa[ks][0] = Qs[qrow * QS_STR + k];
        qa[ks][1] = Qs[(qrow + 8) * QS_STR + k];
        qa[ks][2] = Qs[qrow * QS_STR + k + 4];
        qa[ks][3] = Qs[(qrow + 8) * QS_STR + k + 4];
    }

    float m[2] = {-1e30f, -1e30f};
    float l[2] = {0.0f, 0.0f};
    float o[8][4];
    #pragma unroll
    for (int nf = 0; nf < 8; ++nf)
        #pragma unroll
        for (int j = 0; j < 4; ++j) o[nf][j] = 0.0f;

    for (int t = 0; t <= qt; ++t) {
        __syncthreads();
        const int koff = (b * T + t * 64) * H;
        #pragma unroll
        for (int i = 0; i < 8; ++i) {
            int s = tid + i * 128;
            int r = s >> 4;
            int c4 = (s & 15) * 4;
            uint4 kv = *(const uint4*)&g_K[koff + r * H + c4];
            Ks[r * KS_STR + c4 + 0] = kv.x;
            Ks[r * KS_STR + c4 + 1] = kv.y;
            Ks[r * KS_STR + c4 + 2] = kv.z;
            Ks[r * KS_STR + c4 + 3] = kv.w;
            uint4 vv = *(const uint4*)&g_V[koff + r * H + c4];
            Vs[r * VS_STR + c4 + 0] = vv.x;
            Vs[r * VS_STR + c4 + 1] = vv.y;
            Vs[r * VS_STR + c4 + 2] = vv.z;
            Vs[r * VS_STR + c4 + 3] = vv.w;
        }
        __syncthreads();

        float sf[8][4];
        #pragma unroll
        for (int nf = 0; nf < 8; ++nf)
            #pragma unroll
            for (int j = 0; j < 4; ++j) sf[nf][j] = 0.0f;

        #pragma unroll
        for (int ks = 0; ks < 8; ++ks) {
            int k = ks * 8 + tg;
            #pragma unroll
            for (int nf = 0; nf < 8; ++nf) {
                int key = nf * 8 + g;
                mma_tf32(sf[nf], qa[ks], Ks[key * KS_STR + k], Ks[key * KS_STR + k + 4]);
            }
        }

        const bool last = (t == qt);
        float mnew[2] = {m[0], m[1]};
        #pragma unroll
        for (int nf = 0; nf < 8; ++nf)
            #pragma unroll
            for (int j = 0; j < 4; ++j) {
                int rr = j >> 1;
                float v = sf[nf][j] * scale;
                if (last) {
                    int col = nf * 8 + 2 * tg + (j & 1);
                    int row = wid * 16 + g + rr * 8;
                    if (col > row) v = -1e30f;
                }
                sf[nf][j] = v;
                mnew[rr] = fmaxf(mnew[rr], v);
            }
        #pragma unroll
        for (int rr = 0; rr < 2; ++rr) {
            mnew[rr] = fmaxf(mnew[rr], __shfl_xor_sync(0xffffffffu, mnew[rr], 1));
            mnew[rr] = fmaxf(mnew[rr], __shfl_xor_sync(0xffffffffu, mnew[rr], 2));
        }
        float alpha[2];
        #pragma unroll
        for (int rr = 0; rr < 2; ++rr) {
            alpha[rr] = __expf(m[rr] - mnew[rr]);
            m[rr] = mnew[rr];
        }
        float ls[2] = {0.0f, 0.0f};
        #pragma unroll
        for (int nf = 0; nf < 8; ++nf)
            #pragma unroll
            for (int j = 0; j < 4; ++j) {
                int rr = j >> 1;
                float p = __expf(sf[nf][j] - m[rr]);
                sf[nf][j] = p;
                ls[rr] += p;
            }
        #pragma unroll
        for (int rr = 0; rr < 2; ++rr) {
            ls[rr] += __shfl_xor_sync(0xffffffffu, ls[rr], 1);
            ls[rr] += __shfl_xor_sync(0xffffffffu, ls[rr], 2);
            l[rr] = l[rr] * alpha[rr] + ls[rr];
        }
        #pragma unroll
        for (int nf = 0; nf < 8; ++nf) {
            o[nf][0] *= alpha[0];
            o[nf][1] *= alpha[0];
            o[nf][2] *= alpha[1];
            o[nf][3] *= alpha[1];
        }

        const int prow = wid * 16 + g;
        #pragma unroll
        for (int nf = 0; nf < 8; ++nf) {
            int col = nf * 8 + 2 * tg;
            *(uint2*)&Ps[prow * PS_STR + col] =
                make_uint2(f2tf32(sf[nf][0]), f2tf32(sf[nf][1]));
            *(uint2*)&Ps[(prow + 8) * PS_STR + col] =
                make_uint2(f2tf32(sf[nf][2]), f2tf32(sf[nf][3]));
        }
        __syncthreads();

        #pragma unroll
        for (int ks = 0; ks < 8; ++ks) {
            uint32_t pa[4];
            int k = ks * 8 + tg;
            pa[0] = Ps[prow * PS_STR + k];
            pa[1] = Ps[(prow + 8) * PS_STR + k];
            pa[2] = Ps[prow * PS_STR + k + 4];
            pa[3] = Ps[(prow + 8) * PS_STR + k + 4];
            #pragma unroll
            for (int nf = 0; nf < 8; ++nf) {
                int hh = nf * 8 + g;
                mma_tf32(o[nf], pa,
                         Vs[(ks * 8 + tg) * VS_STR + hh],
                         Vs[(ks * 8 + tg + 4) * VS_STR + hh]);
            }
        }
    }

    const float inv0 = 1.0f / l[0];
    const float inv1 = 1.0f / l[1];
    const int grow = b * T + qt * 64 + wid * 16 + g;
    #pragma unroll
    for (int nf = 0; nf < 8; ++nf) {
        int col = nf * 8 + 2 * tg;
        *(float2*)&out[grow * H + col] =
            make_float2(o[nf][0] * inv0, o[nf][1] * inv0);
        *(float2*)&out[(grow + 8) * H + col] =
            make_float2(o[nf][2] * inv1, o[nf][3] * inv1);
    }
}

// ---------------------------------------------------------------------------
extern "C" void kernel_launch(void* const* d_in, const int* in_sizes, int n_in,
                              void* d_out, int out_size)
{
    const float* x  = (const float*)d_in[0];
    const float* Wq = (const float*)d_in[1];
    const float* Wk = (const float*)d_in[2];
    const float* Wv = (const float*)d_in[3];
    float* out = (float*)d_out;

    qkv_proj_kernel<<<BT / 128, 384>>>(x, Wq, Wk, Wv);

    cudaFuncSetAttribute(attn_kernel,
                         cudaFuncAttributeMaxDynamicSharedMemorySize,
                         ATTN_SMEM_BYTES);
    attn_kernel<<<dim3(T / 64, BATCH), 128, ATTN_SMEM_BYTES>>>(out);
}

// round 5
// speedup vs baseline: 3.2521x; 1.5858x over previous
#include <cuda_runtime.h>
#include <cuda_fp16.h>
#include <cstdint>

#define BATCH 64
#define T 512
#define C 384
#define H 64
#define BT (BATCH*T)

// Q, K projected to fp16 (row-major [row*H+col]); V kept as tf32 bits (row-major).
__device__ __half   g_Q[BT * H];
__device__ __half   g_K[BT * H];
__device__ uint32_t g_V[BT * H];

__device__ __forceinline__ uint32_t f2tf32(float f) {
    uint32_t r;
    asm("cvt.rna.tf32.f32 %0, %1;" : "=r"(r) : "f"(f));
    return r;
}

__device__ __forceinline__ uint32_t pack_h2(float a, float b) {
    __half2 h = __floats2half2_rn(a, b);
    return *(uint32_t*)&h;
}

// tf32 m16n8k8 (fp32 in/out precision path for PV)
__device__ __forceinline__ void mma_tf32(float c[4], const uint32_t a[4],
                                         uint32_t b0, uint32_t b1) {
    asm volatile(
        "mma.sync.aligned.m16n8k8.row.col.f32.tf32.tf32.f32 "
        "{%0,%1,%2,%3}, {%4,%5,%6,%7}, {%8,%9}, {%0,%1,%2,%3};\n"
        : "+f"(c[0]), "+f"(c[1]), "+f"(c[2]), "+f"(c[3])
        : "r"(a[0]), "r"(a[1]), "r"(a[2]), "r"(a[3]), "r"(b0), "r"(b1));
}

// fp16 m16n8k16, fp32 accumulate
__device__ __forceinline__ void mma_f16(float c[4], const uint32_t a[4],
                                        uint32_t b0, uint32_t b1) {
    asm volatile(
        "mma.sync.aligned.m16n8k16.row.col.f32.f16.f16.f32 "
        "{%0,%1,%2,%3}, {%4,%5,%6,%7}, {%8,%9}, {%0,%1,%2,%3};\n"
        : "+f"(c[0]), "+f"(c[1]), "+f"(c[2]), "+f"(c[3])
        : "r"(a[0]), "r"(a[1]), "r"(a[2]), "r"(a[3]), "r"(b0), "r"(b1));
}

// ---------------------------------------------------------------------------
// Kernel 1: QKV projection, fp16 m16n8k16.
// Grid (BT/128, 3). 256 threads = 8 warps as 4(M) x 2(N), warp tile 32x32.
// As2[m][k2]: half2 pairs along k, stride 20 u32 (A-frag bank = (20g+tg)%32 distinct).
// Bs2[k2][n]: half2 pairs along k, stride 72 u32 (B-frag bank = 8tg+g distinct).
// ---------------------------------------------------------------------------
#define QBM 128
#define AS2_STR 20
#define BS2_STR 72

__global__ __launch_bounds__(256) void qkv_proj_kernel(
    const float* __restrict__ x,
    const float* __restrict__ Wq,
    const float* __restrict__ Wk,
    const float* __restrict__ Wv)
{
    __shared__ uint32_t As2[QBM][AS2_STR];   // [m][k/2]
    __shared__ uint32_t Bs2[16][BS2_STR];    // [k/2][n]

    const int wsel = blockIdx.y;
    const float* W = (wsel == 0) ? Wq : ((wsel == 1) ? Wk : Wv);

    const int tid  = threadIdx.x;
    const int lane = tid & 31;
    const int wid  = tid >> 5;
    const int warpM = wid & 3;
    const int warpN = wid >> 2;
    const int g  = lane >> 2;
    const int tg = lane & 3;
    const int row0 = blockIdx.x * QBM;

    float c[2][4][4];
    #pragma unroll
    for (int mf = 0; mf < 2; ++mf)
        #pragma unroll
        for (int nf = 0; nf < 4; ++nf)
            #pragma unroll
            for (int j = 0; j < 4; ++j) c[mf][nf][j] = 0.0f;

    for (int kt = 0; kt < C / 32; ++kt) {
        // x tile 128x32 -> half2 pairs. 1024 float4 slots, 4 per thread.
        #pragma unroll
        for (int i = 0; i < 4; ++i) {
            int s = tid + i * 256;
            int r = s >> 3;
            int c4 = (s & 7) * 4;           // k index, multiple of 4
            float4 v = *(const float4*)&x[(row0 + r) * C + kt * 32 + c4];
            uint2 p = make_uint2(pack_h2(v.x, v.y), pack_h2(v.z, v.w));
            *(uint2*)&As2[r][c4 >> 1] = p;
        }
        // W tile 32x64 -> Bs2[k2][n]: 1024 slots (16 k2 x 64 n), 4 per thread.
        #pragma unroll
        for (int i = 0; i < 4; ++i) {
            int s = tid + i * 256;
            int k2 = s >> 6;
            int n  = s & 63;
            float w0 = W[(kt * 32 + 2 * k2) * H + n];
            float w1 = W[(kt * 32 + 2 * k2 + 1) * H + n];
            Bs2[k2][n] = pack_h2(w0, w1);
        }
        __syncthreads();

        #pragma unroll
        for (int ks = 0; ks < 2; ++ks) {          // two K=16 steps per kt
            const int p = ks * 8 + tg;             // half2 pair index
            uint32_t a[2][4];
            #pragma unroll
            for (int mf = 0; mf < 2; ++mf) {
                int r = warpM * 32 + mf * 16 + g;
                a[mf][0] = As2[r][p];
                a[mf][1] = As2[r + 8][p];
                a[mf][2] = As2[r][p + 4];
                a[mf][3] = As2[r + 8][p + 4];
            }
            #pragma unroll
            for (int nf = 0; nf < 4; ++nf) {
                int n = warpN * 32 + nf * 8 + g;
                uint32_t b0 = Bs2[p][n];
                uint32_t b1 = Bs2[p + 4][n];
                #pragma unroll
                for (int mf = 0; mf < 2; ++mf)
                    mma_f16(c[mf][nf], a[mf], b0, b1);
            }
        }
        __syncthreads();
    }

    // Epilogue: Q,K as fp16 half2 pairs; V as tf32 uint2. All coalesced.
    #pragma unroll
    for (int mf = 0; mf < 2; ++mf) {
        int r = row0 + warpM * 32 + mf * 16 + g;
        #pragma unroll
        for (int nf = 0; nf < 4; ++nf) {
            int col = warpN * 32 + nf * 8 + 2 * tg;
            if (wsel == 2) {
                *(uint2*)&g_V[r * H + col] =
                    make_uint2(f2tf32(c[mf][nf][0]), f2tf32(c[mf][nf][1]));
                *(uint2*)&g_V[(r + 8) * H + col] =
                    make_uint2(f2tf32(c[mf][nf][2]), f2tf32(c[mf][nf][3]));
            } else {
                __half* O = (wsel == 0) ? g_Q : g_K;
                *(uint32_t*)&O[r * H + col]       = pack_h2(c[mf][nf][0], c[mf][nf][1]);
                *(uint32_t*)&O[(r + 8) * H + col] = pack_h2(c[mf][nf][2], c[mf][nf][3]);
            }
        }
    }
}

// ---------------------------------------------------------------------------
// Kernel 2: causal flash attention. QK in fp16 m16n8k16, PV in tf32 m16n8k8.
// Grid (T/64, BATCH), 128 threads = 4 warps; warp owns 16 q-rows x 64 cols.
// ---------------------------------------------------------------------------
#define Q2_STR 36   // u32 stride: frag bank = 4g+tg, conflict free
#define K2_STR 36
#define VS_STR 72
#define PS_STR 68
#define ATTN_SMEM_U32 (64 * (Q2_STR + K2_STR + VS_STR + PS_STR))
#define ATTN_SMEM_BYTES (ATTN_SMEM_U32 * 4)

__global__ __launch_bounds__(128) void attn_kernel(float* __restrict__ out)
{
    extern __shared__ uint32_t sm[];
    uint32_t* Qs2 = sm;                      // [64][36] half2 pairs along h
    uint32_t* Ks2 = Qs2 + 64 * Q2_STR;       // [64][36]
    uint32_t* Vs  = Ks2 + 64 * K2_STR;       // [64][72] tf32
    uint32_t* Ps  = Vs  + 64 * VS_STR;       // [64][68] tf32

    const int tid  = threadIdx.x;
    const int lane = tid & 31;
    const int wid  = tid >> 5;
    const int g    = lane >> 2;
    const int tg   = lane & 3;
    const int qt = blockIdx.x;
    const int b  = blockIdx.y;
    const float scale = 0.125f;

    // Load Q tile: 64 rows x 32 u32 (fp16 pairs). 512 uint4 slots, 4/thread.
    {
        const uint4* src = (const uint4*)(g_Q + (b * T + qt * 64) * H);
        #pragma unroll
        for (int i = 0; i < 4; ++i) {
            int s = tid + i * 128;
            int r = s >> 3;
            int c4 = (s & 7) * 4;
            uint4 v = src[s];
            Qs2[r * Q2_STR + c4 + 0] = v.x;
            Qs2[r * Q2_STR + c4 + 1] = v.y;
            Qs2[r * Q2_STR + c4 + 2] = v.z;
            Qs2[r * Q2_STR + c4 + 3] = v.w;
        }
    }
    __syncthreads();

    // Q fragments (m16n8k16): 4 k-steps, 4 regs each.
    uint32_t qa[4][4];
    const int qrow = wid * 16 + g;
    #pragma unroll
    for (int ks = 0; ks < 4; ++ks) {
        int p = ks * 8 + tg;
        qa[ks][0] = Qs2[qrow * Q2_STR + p];
        qa[ks][1] = Qs2[(qrow + 8) * Q2_STR + p];
        qa[ks][2] = Qs2[qrow * Q2_STR + p + 4];
        qa[ks][3] = Qs2[(qrow + 8) * Q2_STR + p + 4];
    }

    float m[2] = {-1e30f, -1e30f};
    float l[2] = {0.0f, 0.0f};
    float o[8][4];
    #pragma unroll
    for (int nf = 0; nf < 8; ++nf)
        #pragma unroll
        for (int j = 0; j < 4; ++j) o[nf][j] = 0.0f;

    for (int t = 0; t <= qt; ++t) {
        __syncthreads();
        // K tile: 64 x 32 u32 fp16 pairs (512 uint4, 4/thread)
        {
            const uint4* ksrc = (const uint4*)(g_K + (b * T + t * 64) * H);
            #pragma unroll
            for (int i = 0; i < 4; ++i) {
                int s = tid + i * 128;
                int r = s >> 3;
                int c4 = (s & 7) * 4;
                uint4 v = ksrc[s];
                Ks2[r * K2_STR + c4 + 0] = v.x;
                Ks2[r * K2_STR + c4 + 1] = v.y;
                Ks2[r * K2_STR + c4 + 2] = v.z;
                Ks2[r * K2_STR + c4 + 3] = v.w;
            }
        }
        // V tile: 64 x 64 u32 tf32 (1024 uint4-slots/4 = 256... 8/thread via uint4)
        {
            const int voff = (b * T + t * 64) * H;
            #pragma unroll
            for (int i = 0; i < 8; ++i) {
                int s = tid + i * 128;
                int r = s >> 4;
                int c4 = (s & 15) * 4;
                *(uint4*)&Vs[r * VS_STR + c4] = *(const uint4*)&g_V[voff + r * H + c4];
            }
        }
        __syncthreads();

        // --- S = Q K^T (fp16, K=16 per mma) ---
        float sf[8][4];
        #pragma unroll
        for (int nf = 0; nf < 8; ++nf)
            #pragma unroll
            for (int j = 0; j < 4; ++j) sf[nf][j] = 0.0f;

        #pragma unroll
        for (int ks = 0; ks < 4; ++ks) {
            const int p = ks * 8 + tg;
            #pragma unroll
            for (int nf = 0; nf < 8; ++nf) {
                int key = nf * 8 + g;
                mma_f16(sf[nf], qa[ks],
                        Ks2[key * K2_STR + p], Ks2[key * K2_STR + p + 4]);
            }
        }

        // --- online softmax (unchanged) ---
        const bool last = (t == qt);
        float mnew[2] = {m[0], m[1]};
        #pragma unroll
        for (int nf = 0; nf < 8; ++nf)
            #pragma unroll
            for (int j = 0; j < 4; ++j) {
                int rr = j >> 1;
                float v = sf[nf][j] * scale;
                if (last) {
                    int col = nf * 8 + 2 * tg + (j & 1);
                    int row = wid * 16 + g + rr * 8;
                    if (col > row) v = -1e30f;
                }
                sf[nf][j] = v;
                mnew[rr] = fmaxf(mnew[rr], v);
            }
        #pragma unroll
        for (int rr = 0; rr < 2; ++rr) {
            mnew[rr] = fmaxf(mnew[rr], __shfl_xor_sync(0xffffffffu, mnew[rr], 1));
            mnew[rr] = fmaxf(mnew[rr], __shfl_xor_sync(0xffffffffu, mnew[rr], 2));
        }
        float alpha[2];
        #pragma unroll
        for (int rr = 0; rr < 2; ++rr) {
            alpha[rr] = __expf(m[rr] - mnew[rr]);
            m[rr] = mnew[rr];
        }
        float ls[2] = {0.0f, 0.0f};
        #pragma unroll
        for (int nf = 0; nf < 8; ++nf)
            #pragma unroll
            for (int j = 0; j < 4; ++j) {
                int rr = j >> 1;
                float pexp = __expf(sf[nf][j] - m[rr]);
                sf[nf][j] = pexp;
                ls[rr] += pexp;
            }
        #pragma unroll
        for (int rr = 0; rr < 2; ++rr) {
            ls[rr] += __shfl_xor_sync(0xffffffffu, ls[rr], 1);
            ls[rr] += __shfl_xor_sync(0xffffffffu, ls[rr], 2);
            l[rr] = l[rr] * alpha[rr] + ls[rr];
        }
        #pragma unroll
        for (int nf = 0; nf < 8; ++nf) {
            o[nf][0] *= alpha[0];
            o[nf][1] *= alpha[0];
            o[nf][2] *= alpha[1];
            o[nf][3] *= alpha[1];
        }

        // --- P to smem (tf32) for PV A-fragments ---
        const int prow = wid * 16 + g;
        #pragma unroll
        for (int nf = 0; nf < 8; ++nf) {
            int col = nf * 8 + 2 * tg;
            *(uint2*)&Ps[prow * PS_STR + col] =
                make_uint2(f2tf32(sf[nf][0]), f2tf32(sf[nf][1]));
            *(uint2*)&Ps[(prow + 8) * PS_STR + col] =
                make_uint2(f2tf32(sf[nf][2]), f2tf32(sf[nf][3]));
        }
        __syncthreads();

        // --- O += P V (tf32, K=8 per mma) ---
        #pragma unroll
        for (int ks = 0; ks < 8; ++ks) {
            uint32_t pa[4];
            int k = ks * 8 + tg;
            pa[0] = Ps[prow * PS_STR + k];
            pa[1] = Ps[(prow + 8) * PS_STR + k];
            pa[2] = Ps[prow * PS_STR + k + 4];
            pa[3] = Ps[(prow + 8) * PS_STR + k + 4];
            #pragma unroll
            for (int nf = 0; nf < 8; ++nf) {
                int hh = nf * 8 + g;
                mma_tf32(o[nf], pa,
                         Vs[(ks * 8 + tg) * VS_STR + hh],
                         Vs[(ks * 8 + tg + 4) * VS_STR + hh]);
            }
        }
    }

    const float inv0 = 1.0f / l[0];
    const float inv1 = 1.0f / l[1];
    const int grow = b * T + qt * 64 + wid * 16 + g;
    #pragma unroll
    for (int nf = 0; nf < 8; ++nf) {
        int col = nf * 8 + 2 * tg;
        *(float2*)&out[grow * H + col] =
            make_float2(o[nf][0] * inv0, o[nf][1] * inv0);
        *(float2*)&out[(grow + 8) * H + col] =
            make_float2(o[nf][2] * inv1, o[nf][3] * inv1);
    }
}

// ---------------------------------------------------------------------------
extern "C" void kernel_launch(void* const* d_in, const int* in_sizes, int n_in,
                              void* d_out, int out_size)
{
    const float* x  = (const float*)d_in[0];
    const float* Wq = (const float*)d_in[1];
    const float* Wk = (const float*)d_in[2];
    const float* Wv = (const float*)d_in[3];
    float* out = (float*)d_out;

    qkv_proj_kernel<<<dim3(BT / QBM, 3), 256>>>(x, Wq, Wk, Wv);

    cudaFuncSetAttribute(attn_kernel,
                         cudaFuncAttributeMaxDynamicSharedMemorySize,
                         ATTN_SMEM_BYTES);
    attn_kernel<<<dim3(T / 64, BATCH), 128, ATTN_SMEM_BYTES>>>(out);
}

// round 6
// speedup vs baseline: 3.9411x; 1.2119x over previous
#include <cuda_runtime.h>
#include <cuda_fp16.h>
#include <cstdint>

#define BATCH 64
#define T 512
#define C 384
#define H 64
#define BT (BATCH*T)

// Q, K, V projected to fp16, row-major [row*H + col].
__device__ __half g_Q[BT * H];
__device__ __half g_K[BT * H];
__device__ __half g_V[BT * H];
// Weights pre-packed to fp16 half2 pairs along k: [mat][k2][n], k2 = k/2 (192), n (64).
__device__ uint32_t g_W16[3 * 192 * 64];

__device__ __forceinline__ uint32_t pack_h2(float a, float b) {
    __half2 h = __floats2half2_rn(a, b);
    return *(uint32_t*)&h;
}

// fp16 m16n8k16, fp32 accumulate
__device__ __forceinline__ void mma_f16(float c[4], const uint32_t a[4],
                                        uint32_t b0, uint32_t b1) {
    asm volatile(
        "mma.sync.aligned.m16n8k16.row.col.f32.f16.f16.f32 "
        "{%0,%1,%2,%3}, {%4,%5,%6,%7}, {%8,%9}, {%0,%1,%2,%3};\n"
        : "+f"(c[0]), "+f"(c[1]), "+f"(c[2]), "+f"(c[3])
        : "r"(a[0]), "r"(a[1]), "r"(a[2]), "r"(a[3]), "r"(b0), "r"(b1));
}

// ---------------------------------------------------------------------------
// Kernel 0: pack W{q,k,v} fp32 -> fp16 half2 pairs along k. 36864 elements.
// ---------------------------------------------------------------------------
__global__ __launch_bounds__(256) void pack_w_kernel(
    const float* __restrict__ Wq,
    const float* __restrict__ Wk,
    const float* __restrict__ Wv)
{
    int idx = blockIdx.x * 256 + threadIdx.x;      // 144 blocks exactly
    int mat = idx / (192 * 64);
    int rem = idx - mat * (192 * 64);
    int k2 = rem >> 6;
    int n  = rem & 63;
    const float* W = (mat == 0) ? Wq : ((mat == 1) ? Wk : Wv);
    g_W16[idx] = pack_h2(W[(2 * k2) * H + n], W[(2 * k2 + 1) * H + n]);
}

// ---------------------------------------------------------------------------
// Kernel 1: QKV projection, fp16 m16n8k16. Grid (BT/128, 3), 256 threads
// = 8 warps as 4(M) x 2(N), warp tile 32x32. W B-fragments read straight
// from gmem (L1-hot, 48KB per matrix). x tile double-buffered, 1 sync/kt.
// ---------------------------------------------------------------------------
#define AS2_STR 20

__global__ __launch_bounds__(256) void qkv_proj_kernel(const float* __restrict__ x)
{
    __shared__ uint32_t As2[2][128][AS2_STR];   // x tile fp16 pairs [m][k2]

    const int mat = blockIdx.y;
    const uint32_t* Wp = g_W16 + mat * 192 * 64;

    const int tid  = threadIdx.x;
    const int lane = tid & 31;
    const int wid  = tid >> 5;
    const int warpM = wid & 3;
    const int warpN = wid >> 2;
    const int g  = lane >> 2;
    const int tg = lane & 3;
    const int row0 = blockIdx.x * 128;

    float c[2][4][4];
    #pragma unroll
    for (int mf = 0; mf < 2; ++mf)
        #pragma unroll
        for (int nf = 0; nf < 4; ++nf)
            #pragma unroll
            for (int j = 0; j < 4; ++j) c[mf][nf][j] = 0.0f;

    // initial x tile (kt=0) into buf 0
    #pragma unroll
    for (int i = 0; i < 4; ++i) {
        int s = tid + i * 256;
        int r = s >> 3;
        int c4 = (s & 7) * 4;
        float4 v = *(const float4*)&x[(row0 + r) * C + c4];
        *(uint2*)&As2[0][r][c4 >> 1] = make_uint2(pack_h2(v.x, v.y), pack_h2(v.z, v.w));
    }

    for (int kt = 0; kt < 12; ++kt) {
        const int buf = kt & 1;
        __syncthreads();

        // prefetch next x tile into registers
        float4 xv[4];
        const bool pf = (kt < 11);
        if (pf) {
            #pragma unroll
            for (int i = 0; i < 4; ++i) {
                int s = tid + i * 256;
                int r = s >> 3;
                int c4 = (s & 7) * 4;
                xv[i] = *(const float4*)&x[(row0 + r) * C + (kt + 1) * 32 + c4];
            }
        }

        #pragma unroll
        for (int ks = 0; ks < 2; ++ks) {
            const int p = ks * 8 + tg;
            uint32_t a[2][4];
            #pragma unroll
            for (int mf = 0; mf < 2; ++mf) {
                int r = warpM * 32 + mf * 16 + g;
                a[mf][0] = As2[buf][r][p];
                a[mf][1] = As2[buf][r + 8][p];
                a[mf][2] = As2[buf][r][p + 4];
                a[mf][3] = As2[buf][r + 8][p + 4];
            }
            const int prow = kt * 16 + p;
            #pragma unroll
            for (int nf = 0; nf < 4; ++nf) {
                int n = warpN * 32 + nf * 8 + g;
                uint32_t b0 = Wp[prow * 64 + n];
                uint32_t b1 = Wp[(prow + 4) * 64 + n];
                #pragma unroll
                for (int mf = 0; mf < 2; ++mf)
                    mma_f16(c[mf][nf], a[mf], b0, b1);
            }
        }

        if (pf) {
            #pragma unroll
            for (int i = 0; i < 4; ++i) {
                int s = tid + i * 256;
                int r = s >> 3;
                int c4 = (s & 7) * 4;
                *(uint2*)&As2[buf ^ 1][r][c4 >> 1] =
                    make_uint2(pack_h2(xv[i].x, xv[i].y), pack_h2(xv[i].z, xv[i].w));
            }
        }
    }

    __half* O = (mat == 0) ? g_Q : ((mat == 1) ? g_K : g_V);
    #pragma unroll
    for (int mf = 0; mf < 2; ++mf) {
        int r = row0 + warpM * 32 + mf * 16 + g;
        #pragma unroll
        for (int nf = 0; nf < 4; ++nf) {
            int col = warpN * 32 + nf * 8 + 2 * tg;
            *(uint32_t*)&O[r * H + col]       = pack_h2(c[mf][nf][0], c[mf][nf][1]);
            *(uint32_t*)&O[(r + 8) * H + col] = pack_h2(c[mf][nf][2], c[mf][nf][3]);
        }
    }
}

// ---------------------------------------------------------------------------
// Kernel 2: causal flash attention, all-fp16 mma, P kept in registers,
// double-buffered K/V, one barrier per tile. Grid (BATCH, T/64), 128 thr.
// ---------------------------------------------------------------------------
#define Q2_STR 36
#define K2_STR 36
#define V2_STR 72

__global__ __launch_bounds__(128) void attn_kernel(float* __restrict__ out)
{
    __shared__ uint32_t Qs2[64 * Q2_STR];        // fp16 pairs along h
    __shared__ uint32_t K2[2][64 * K2_STR];      // fp16 pairs along h
    __shared__ uint32_t V2[2][32 * V2_STR];      // fp16 pairs along KEY dim

    const int tid  = threadIdx.x;
    const int lane = tid & 31;
    const int wid  = tid >> 5;
    const int g    = lane >> 2;
    const int tg   = lane & 3;
    const int b  = blockIdx.x;
    const int qt = blockIdx.y;
    const float scale = 0.125f;

    // ---- Q tile ----
    {
        const uint4* qsrc = (const uint4*)(g_Q + (b * T + qt * 64) * H);
        #pragma unroll
        for (int i = 0; i < 4; ++i) {
            int s = tid + i * 128;
            int r = s >> 3;
            int c4 = (s & 7) * 4;
            *(uint4*)&Qs2[r * Q2_STR + c4] = qsrc[s];
        }
    }
    // ---- K/V tile 0 into buf 0 ----
    {
        const uint4* ksrc = (const uint4*)(g_K + (b * T) * H);
        #pragma unroll
        for (int i = 0; i < 4; ++i) {
            int s = tid + i * 128;
            *(uint4*)&K2[0][(s >> 3) * K2_STR + (s & 7) * 4] = ksrc[s];
        }
        #pragma unroll
        for (int i = 0; i < 2; ++i) {
            int s = tid + i * 128;
            int k2 = s >> 3;
            int h0 = (s & 7) * 8;
            const __half* vb = g_V + (b * T + 2 * k2) * H + h0;
            uint4 ea = *(const uint4*)vb;
            uint4 eb = *(const uint4*)(vb + H);
            uint32_t* dst = &V2[0][k2 * V2_STR + h0];
            uint4 o0 = make_uint4(__byte_perm(ea.x, eb.x, 0x5410), __byte_perm(ea.x, eb.x, 0x7632),
                                  __byte_perm(ea.y, eb.y, 0x5410), __byte_perm(ea.y, eb.y, 0x7632));
            uint4 o1 = make_uint4(__byte_perm(ea.z, eb.z, 0x5410), __byte_perm(ea.z, eb.z, 0x7632),
                                  __byte_perm(ea.w, eb.w, 0x5410), __byte_perm(ea.w, eb.w, 0x7632));
            *(uint4*)&dst[0] = o0;
            *(uint4*)&dst[4] = o1;
        }
    }
    __syncthreads();

    // ---- Q fragments (register resident for all iterations) ----
    uint32_t qa[4][4];
    const int qrow = wid * 16 + g;
    #pragma unroll
    for (int ks = 0; ks < 4; ++ks) {
        int p = ks * 8 + tg;
        qa[ks][0] = Qs2[qrow * Q2_STR + p];
        qa[ks][1] = Qs2[(qrow + 8) * Q2_STR + p];
        qa[ks][2] = Qs2[qrow * Q2_STR + p + 4];
        qa[ks][3] = Qs2[(qrow + 8) * Q2_STR + p + 4];
    }

    float m[2] = {-1e30f, -1e30f};
    float l[2] = {0.0f, 0.0f};
    float o[8][4];
    #pragma unroll
    for (int nf = 0; nf < 8; ++nf)
        #pragma unroll
        for (int j = 0; j < 4; ++j) o[nf][j] = 0.0f;

    for (int t = 0; t <= qt; ++t) {
        const int buf = t & 1;
        const bool pf = (t < qt);

        // prefetch next K/V tile into registers
        uint4 kp[4], ve[2], vo[2];
        if (pf) {
            const uint4* ksrc = (const uint4*)(g_K + (b * T + (t + 1) * 64) * H);
            #pragma unroll
            for (int i = 0; i < 4; ++i) kp[i] = ksrc[tid + i * 128];
            #pragma unroll
            for (int i = 0; i < 2; ++i) {
                int s = tid + i * 128;
                int k2 = s >> 3;
                int h0 = (s & 7) * 8;
                const __half* vb = g_V + (b * T + (t + 1) * 64 + 2 * k2) * H + h0;
                ve[i] = *(const uint4*)vb;
                vo[i] = *(const uint4*)(vb + H);
            }
        }

        // --- S = Q K^T ---
        float sf[8][4];
        #pragma unroll
        for (int nf = 0; nf < 8; ++nf)
            #pragma unroll
            for (int j = 0; j < 4; ++j) sf[nf][j] = 0.0f;

        #pragma unroll
        for (int ks = 0; ks < 4; ++ks) {
            const int p = ks * 8 + tg;
            #pragma unroll
            for (int nf = 0; nf < 8; ++nf) {
                int key = nf * 8 + g;
                mma_f16(sf[nf], qa[ks],
                        K2[buf][key * K2_STR + p], K2[buf][key * K2_STR + p + 4]);
            }
        }

        // --- store prefetched tile into other buffer (LDG long done) ---
        if (pf) {
            #pragma unroll
            for (int i = 0; i < 4; ++i) {
                int s = tid + i * 128;
                *(uint4*)&K2[buf ^ 1][(s >> 3) * K2_STR + (s & 7) * 4] = kp[i];
            }
            #pragma unroll
            for (int i = 0; i < 2; ++i) {
                int s = tid + i * 128;
                int k2 = s >> 3;
                int h0 = (s & 7) * 8;
                uint32_t* dst = &V2[buf ^ 1][k2 * V2_STR + h0];
                uint4 o0 = make_uint4(__byte_perm(ve[i].x, vo[i].x, 0x5410), __byte_perm(ve[i].x, vo[i].x, 0x7632),
                                      __byte_perm(ve[i].y, vo[i].y, 0x5410), __byte_perm(ve[i].y, vo[i].y, 0x7632));
                uint4 o1 = make_uint4(__byte_perm(ve[i].z, vo[i].z, 0x5410), __byte_perm(ve[i].z, vo[i].z, 0x7632),
                                      __byte_perm(ve[i].w, vo[i].w, 0x5410), __byte_perm(ve[i].w, vo[i].w, 0x7632));
                *(uint4*)&dst[0] = o0;
                *(uint4*)&dst[4] = o1;
            }
        }

        // --- online softmax ---
        const bool last = (t == qt);
        float mnew[2] = {m[0], m[1]};
        #pragma unroll
        for (int nf = 0; nf < 8; ++nf)
            #pragma unroll
            for (int j = 0; j < 4; ++j) {
                int rr = j >> 1;
                float v = sf[nf][j] * scale;
                if (last) {
                    int col = nf * 8 + 2 * tg + (j & 1);
                    int row = wid * 16 + g + rr * 8;
                    if (col > row) v = -1e30f;
                }
                sf[nf][j] = v;
                mnew[rr] = fmaxf(mnew[rr], v);
            }
        #pragma unroll
        for (int rr = 0; rr < 2; ++rr) {
            mnew[rr] = fmaxf(mnew[rr], __shfl_xor_sync(0xffffffffu, mnew[rr], 1));
            mnew[rr] = fmaxf(mnew[rr], __shfl_xor_sync(0xffffffffu, mnew[rr], 2));
        }
        float alpha[2];
        #pragma unroll
        for (int rr = 0; rr < 2; ++rr) {
            alpha[rr] = __expf(m[rr] - mnew[rr]);
            m[rr] = mnew[rr];
        }
        float ls[2] = {0.0f, 0.0f};
        #pragma unroll
        for (int nf = 0; nf < 8; ++nf)
            #pragma unroll
            for (int j = 0; j < 4; ++j) {
                int rr = j >> 1;
                float pexp = __expf(sf[nf][j] - m[rr]);
                sf[nf][j] = pexp;
                ls[rr] += pexp;
            }
        #pragma unroll
        for (int rr = 0; rr < 2; ++rr) {
            ls[rr] += __shfl_xor_sync(0xffffffffu, ls[rr], 1);
            ls[rr] += __shfl_xor_sync(0xffffffffu, ls[rr], 2);
            l[rr] = l[rr] * alpha[rr] + ls[rr];
        }
        #pragma unroll
        for (int nf = 0; nf < 8; ++nf) {
            o[nf][0] *= alpha[0];
            o[nf][1] *= alpha[0];
            o[nf][2] *= alpha[1];
            o[nf][3] *= alpha[1];
        }

        // --- O += P V : P fragments built in registers (no smem round-trip) ---
        #pragma unroll
        for (int ks = 0; ks < 4; ++ks) {
            uint32_t pa[4];
            pa[0] = pack_h2(sf[2 * ks][0],     sf[2 * ks][1]);
            pa[1] = pack_h2(sf[2 * ks][2],     sf[2 * ks][3]);
            pa[2] = pack_h2(sf[2 * ks + 1][0], sf[2 * ks + 1][1]);
            pa[3] = pack_h2(sf[2 * ks + 1][2], sf[2 * ks + 1][3]);
            #pragma unroll
            for (int nf = 0; nf < 8; ++nf) {
                int hh = nf * 8 + g;
                mma_f16(o[nf], pa,
                        V2[buf][(ks * 8 + tg) * V2_STR + hh],
                        V2[buf][(ks * 8 + tg + 4) * V2_STR + hh]);
            }
        }

        __syncthreads();
    }

    const float inv0 = 1.0f / l[0];
    const float inv1 = 1.0f / l[1];
    const int grow = b * T + qt * 64 + wid * 16 + g;
    #pragma unroll
    for (int nf = 0; nf < 8; ++nf) {
        int col = nf * 8 + 2 * tg;
        *(float2*)&out[grow * H + col] =
            make_float2(o[nf][0] * inv0, o[nf][1] * inv0);
        *(float2*)&out[(grow + 8) * H + col] =
            make_float2(o[nf][2] * inv1, o[nf][3] * inv1);
    }
}

// ---------------------------------------------------------------------------
extern "C" void kernel_launch(void* const* d_in, const int* in_sizes, int n_in,
                              void* d_out, int out_size)
{
    const float* x  = (const float*)d_in[0];
    const float* Wq = (const float*)d_in[1];
    const float* Wk = (const float*)d_in[2];
    const float* Wv = (const float*)d_in[3];
    float* out = (float*)d_out;

    pack_w_kernel<<<144, 256>>>(Wq, Wk, Wv);
    qkv_proj_kernel<<<dim3(BT / 128, 3), 256>>>(x);
    attn_kernel<<<dim3(BATCH, T / 64), 128>>>(out);
}

// round 8
// speedup vs baseline: 4.5191x; 1.1467x over previous
#include <cuda_runtime.h>
#include <cuda_fp16.h>
#include <cstdint>

#define BATCH 64
#define T 512
#define C 384
#define H 64
#define BT (BATCH*T)

// Q, K, V projected to fp16, row-major [row*H + col].
__device__ __half g_Q[BT * H];
__device__ __half g_K[BT * H];
__device__ __half g_V[BT * H];
// Weights pre-packed to fp16 half2 pairs along k: [mat][k2][n], k2 = k/2 (192), n (64).
__device__ uint32_t g_W16[3 * 192 * 64];

__device__ __forceinline__ uint32_t pack_h2(float a, float b) {
    __half2 h = __floats2half2_rn(a, b);
    return *(uint32_t*)&h;
}

// fp16 m16n8k16, fp32 accumulate
__device__ __forceinline__ void mma_f16(float c[4], const uint32_t a[4],
                                        uint32_t b0, uint32_t b1) {
    asm volatile(
        "mma.sync.aligned.m16n8k16.row.col.f32.f16.f16.f32 "
        "{%0,%1,%2,%3}, {%4,%5,%6,%7}, {%8,%9}, {%0,%1,%2,%3};\n"
        : "+f"(c[0]), "+f"(c[1]), "+f"(c[2]), "+f"(c[3])
        : "r"(a[0]), "r"(a[1]), "r"(a[2]), "r"(a[3]), "r"(b0), "r"(b1));
}

// ---------------------------------------------------------------------------
// Kernel 0: pack W{q,k,v} fp32 -> fp16 half2 pairs along k. 36864 elements.
// ---------------------------------------------------------------------------
__global__ __launch_bounds__(256) void pack_w_kernel(
    const float* __restrict__ Wq,
    const float* __restrict__ Wk,
    const float* __restrict__ Wv)
{
    int idx = blockIdx.x * 256 + threadIdx.x;      // 144 blocks exactly
    int mat = idx / (192 * 64);
    int rem = idx - mat * (192 * 64);
    int k2 = rem >> 6;
    int n  = rem & 63;
    const float* W = (mat == 0) ? Wq : ((mat == 1) ? Wk : Wv);
    g_W16[idx] = pack_h2(W[(2 * k2) * H + n], W[(2 * k2 + 1) * H + n]);
}

// ---------------------------------------------------------------------------
// Kernel 1: QKV projection, fp16 m16n8k16.
// Grid (3, BT/128) — mat is the FAST grid dim so all 3 matrices for the same
// x rows launch adjacently (x tile L2-hot; x DRAM traffic ~1x).
// 256 threads = 8 warps as 4(M) x 2(N), warp tile 32x32.
// Whole W (fp16) resident in smem. x tile double-buffered, one barrier per kt.
// ---------------------------------------------------------------------------
#define AS2_STR 20
#define WS_STR 68
#define QKV_SMEM_U32 (192 * WS_STR + 2 * 128 * AS2_STR)
#define QKV_SMEM_BYTES (QKV_SMEM_U32 * 4)

__global__ __launch_bounds__(256) void qkv_proj_kernel(const float* __restrict__ x)
{
    extern __shared__ uint32_t sm_qkv[];
    uint32_t* Ws = sm_qkv;                         // [192][68]
    uint32_t (*As2)[128][AS2_STR] =
        (uint32_t (*)[128][AS2_STR])(sm_qkv + 192 * WS_STR);

    const int mat = blockIdx.x;
    const int tid  = threadIdx.x;
    const int lane = tid & 31;
    const int wid  = tid >> 5;
    const int warpM = wid & 3;
    const int warpN = wid >> 2;
    const int g  = lane >> 2;
    const int tg = lane & 3;
    const int row0 = blockIdx.y * 128;

    // Load entire W16 slice into smem: 12288 u32 = 3072 uint4, 12 per thread.
    {
        const uint4* wsrc = (const uint4*)(g_W16 + mat * 192 * 64);
        #pragma unroll
        for (int i = 0; i < 12; ++i) {
            int s = tid + i * 256;
            int k2 = s >> 4;
            int n4 = (s & 15) * 4;
            *(uint4*)&Ws[k2 * WS_STR + n4] = wsrc[s];
        }
    }

    float c[2][4][4];
    #pragma unroll
    for (int mf = 0; mf < 2; ++mf)
        #pragma unroll
        for (int nf = 0; nf < 4; ++nf)
            #pragma unroll
            for (int j = 0; j < 4; ++j) c[mf][nf][j] = 0.0f;

    // initial x tile (kt=0) into buf 0
    #pragma unroll
    for (int i = 0; i < 4; ++i) {
        int s = tid + i * 256;
        int r = s >> 3;
        int c4 = (s & 7) * 4;
        float4 v = *(const float4*)&x[(row0 + r) * C + c4];
        *(uint2*)&As2[0][r][c4 >> 1] = make_uint2(pack_h2(v.x, v.y), pack_h2(v.z, v.w));
    }

    for (int kt = 0; kt < 12; ++kt) {
        const int buf = kt & 1;
        __syncthreads();

        float4 xv[4];
        const bool pf = (kt < 11);
        if (pf) {
            #pragma unroll
            for (int i = 0; i < 4; ++i) {
                int s = tid + i * 256;
                int r = s >> 3;
                int c4 = (s & 7) * 4;
                xv[i] = *(const float4*)&x[(row0 + r) * C + (kt + 1) * 32 + c4];
            }
        }

        #pragma unroll
        for (int ks = 0; ks < 2; ++ks) {
            const int p = ks * 8 + tg;
            uint32_t a[2][4];
            #pragma unroll
            for (int mf = 0; mf < 2; ++mf) {
                int r = warpM * 32 + mf * 16 + g;
                a[mf][0] = As2[buf][r][p];
                a[mf][1] = As2[buf][r + 8][p];
                a[mf][2] = As2[buf][r][p + 4];
                a[mf][3] = As2[buf][r + 8][p + 4];
            }
            const int prow = kt * 16 + p;
            #pragma unroll
            for (int nf = 0; nf < 4; ++nf) {
                int n = warpN * 32 + nf * 8 + g;
                uint32_t b0 = Ws[prow * WS_STR + n];
                uint32_t b1 = Ws[(prow + 4) * WS_STR + n];
                #pragma unroll
                for (int mf = 0; mf < 2; ++mf)
                    mma_f16(c[mf][nf], a[mf], b0, b1);
            }
        }

        if (pf) {
            #pragma unroll
            for (int i = 0; i < 4; ++i) {
                int s = tid + i * 256;
                int r = s >> 3;
                int c4 = (s & 7) * 4;
                *(uint2*)&As2[buf ^ 1][r][c4 >> 1] =
                    make_uint2(pack_h2(xv[i].x, xv[i].y), pack_h2(xv[i].z, xv[i].w));
            }
        }
    }

    __half* O = (mat == 0) ? g_Q : ((mat == 1) ? g_K : g_V);
    #pragma unroll
    for (int mf = 0; mf < 2; ++mf) {
        int r = row0 + warpM * 32 + mf * 16 + g;
        #pragma unroll
        for (int nf = 0; nf < 4; ++nf) {
            int col = warpN * 32 + nf * 8 + 2 * tg;
            *(uint32_t*)&O[r * H + col]       = pack_h2(c[mf][nf][0], c[mf][nf][1]);
            *(uint32_t*)&O[(r + 8) * H + col] = pack_h2(c[mf][nf][2], c[mf][nf][3]);
        }
    }
}

// ---------------------------------------------------------------------------
// Kernel 2: causal flash attention, all-fp16 mma, P in registers,
// double-buffered K/V, one barrier per tile. Grid (BATCH, T/64), 128 thr.
// HEAVY TILES FIRST: qt = 7 - blockIdx.y so 8-iter blocks launch first.
// ---------------------------------------------------------------------------
#define Q2_STR 36
#define K2_STR 36
#define V2_STR 72

__global__ __launch_bounds__(128) void attn_kernel(float* __restrict__ out)
{
    __shared__ uint32_t Qs2[64 * Q2_STR];        // fp16 pairs along h
    __shared__ uint32_t K2[2][64 * K2_STR];      // fp16 pairs along h
    __shared__ uint32_t V2[2][32 * V2_STR];      // fp16 pairs along KEY dim

    const int tid  = threadIdx.x;
    const int lane = tid & 31;
    const int wid  = tid >> 5;
    const int g    = lane >> 2;
    const int tg   = lane & 3;
    const int b  = blockIdx.x;
    const int qt = (T / 64 - 1) - blockIdx.y;    // heavy first
    const float scale = 0.125f;

    // ---- Q tile ----
    {
        const uint4* qsrc = (const uint4*)(g_Q + (b * T + qt * 64) * H);
        #pragma unroll
        for (int i = 0; i < 4; ++i) {
            int s = tid + i * 128;
            int r = s >> 3;
            int c4 = (s & 7) * 4;
            *(uint4*)&Qs2[r * Q2_STR + c4] = qsrc[s];
        }
    }
    // ---- K/V tile 0 into buf 0 ----
    {
        const uint4* ksrc = (const uint4*)(g_K + (b * T) * H);
        #pragma unroll
        for (int i = 0; i < 4; ++i) {
            int s = tid + i * 128;
            *(uint4*)&K2[0][(s >> 3) * K2_STR + (s & 7) * 4] = ksrc[s];
        }
        #pragma unroll
        for (int i = 0; i < 2; ++i) {
            int s = tid + i * 128;
            int k2 = s >> 3;
            int h0 = (s & 7) * 8;
            const __half* vb = g_V + (b * T + 2 * k2) * H + h0;
            uint4 ea = *(const uint4*)vb;
            uint4 eb = *(const uint4*)(vb + H);
            uint32_t* dst = &V2[0][k2 * V2_STR + h0];
            uint4 o0 = make_uint4(__byte_perm(ea.x, eb.x, 0x5410), __byte_perm(ea.x, eb.x, 0x7632),
                                  __byte_perm(ea.y, eb.y, 0x5410), __byte_perm(ea.y, eb.y, 0x7632));
            uint4 o1 = make_uint4(__byte_perm(ea.z, eb.z, 0x5410), __byte_perm(ea.z, eb.z, 0x7632),
                                  __byte_perm(ea.w, eb.w, 0x5410), __byte_perm(ea.w, eb.w, 0x7632));
            *(uint4*)&dst[0] = o0;
            *(uint4*)&dst[4] = o1;
        }
    }
    __syncthreads();

    // ---- Q fragments (register resident) ----
    uint32_t qa[4][4];
    const int qrow = wid * 16 + g;
    #pragma unroll
    for (int ks = 0; ks < 4; ++ks) {
        int p = ks * 8 + tg;
        qa[ks][0] = Qs2[qrow * Q2_STR + p];
        qa[ks][1] = Qs2[(qrow + 8) * Q2_STR + p];
        qa[ks][2] = Qs2[qrow * Q2_STR + p + 4];
        qa[ks][3] = Qs2[(qrow + 8) * Q2_STR + p + 4];
    }

    float m[2] = {-1e30f, -1e30f};
    float l[2] = {0.0f, 0.0f};
    float o[8][4];
    #pragma unroll
    for (int nf = 0; nf < 8; ++nf)
        #pragma unroll
        for (int j = 0; j < 4; ++j) o[nf][j] = 0.0f;

    for (int t = 0; t <= qt; ++t) {
        const int buf = t & 1;
        const bool pf = (t < qt);

        uint4 kp[4], ve[2], vo[2];
        if (pf) {
            const uint4* ksrc = (const uint4*)(g_K + (b * T + (t + 1) * 64) * H);
            #pragma unroll
            for (int i = 0; i < 4; ++i) kp[i] = ksrc[tid + i * 128];
            #pragma unroll
            for (int i = 0; i < 2; ++i) {
                int s = tid + i * 128;
                int k2 = s >> 3;
                int h0 = (s & 7) * 8;
                const __half* vb = g_V + (b * T + (t + 1) * 64 + 2 * k2) * H + h0;
                ve[i] = *(const uint4*)vb;
                vo[i] = *(const uint4*)(vb + H);
            }
        }

        // --- S = Q K^T ---
        float sf[8][4];
        #pragma unroll
        for (int nf = 0; nf < 8; ++nf)
            #pragma unroll
            for (int j = 0; j < 4; ++j) sf[nf][j] = 0.0f;

        #pragma unroll
        for (int ks = 0; ks < 4; ++ks) {
            const int p = ks * 8 + tg;
            #pragma unroll
            for (int nf = 0; nf < 8; ++nf) {
                int key = nf * 8 + g;
                mma_f16(sf[nf], qa[ks],
                        K2[buf][key * K2_STR + p], K2[buf][key * K2_STR + p + 4]);
            }
        }

        if (pf) {
            #pragma unroll
            for (int i = 0; i < 4; ++i) {
                int s = tid + i * 128;
                *(uint4*)&K2[buf ^ 1][(s >> 3) * K2_STR + (s & 7) * 4] = kp[i];
            }
            #pragma unroll
            for (int i = 0; i < 2; ++i) {
                int s = tid + i * 128;
                int k2 = s >> 3;
                int h0 = (s & 7) * 8;
                uint32_t* dst = &V2[buf ^ 1][k2 * V2_STR + h0];
                uint4 o0 = make_uint4(__byte_perm(ve[i].x, vo[i].x, 0x5410), __byte_perm(ve[i].x, vo[i].x, 0x7632),
                                      __byte_perm(ve[i].y, vo[i].y, 0x5410), __byte_perm(ve[i].y, vo[i].y, 0x7632));
                uint4 o1 = make_uint4(__byte_perm(ve[i].z, vo[i].z, 0x5410), __byte_perm(ve[i].z, vo[i].z, 0x7632),
                                      __byte_perm(ve[i].w, vo[i].w, 0x5410), __byte_perm(ve[i].w, vo[i].w, 0x7632));
                *(uint4*)&dst[0] = o0;
                *(uint4*)&dst[4] = o1;
            }
        }

        // --- online softmax ---
        const bool last = (t == qt);
        float mnew[2] = {m[0], m[1]};
        #pragma unroll
        for (int nf = 0; nf < 8; ++nf)
            #pragma unroll
            for (int j = 0; j < 4; ++j) {
                int rr = j >> 1;
                float v = sf[nf][j] * scale;
                if (last) {
                    int col = nf * 8 + 2 * tg + (j & 1);
                    int row = wid * 16 + g + rr * 8;
                    if (col > row) v = -1e30f;
                }
                sf[nf][j] = v;
                mnew[rr] = fmaxf(mnew[rr], v);
            }
        #pragma unroll
        for (int rr = 0; rr < 2; ++rr) {
            mnew[rr] = fmaxf(mnew[rr], __shfl_xor_sync(0xffffffffu, mnew[rr], 1));
            mnew[rr] = fmaxf(mnew[rr], __shfl_xor_sync(0xffffffffu, mnew[rr], 2));
        }
        float alpha[2];
        #pragma unroll
        for (int rr = 0; rr < 2; ++rr) {
            alpha[rr] = __expf(m[rr] - mnew[rr]);
            m[rr] = mnew[rr];
        }
        float ls[2] = {0.0f, 0.0f};
        #pragma unroll
        for (int nf = 0; nf < 8; ++nf)
            #pragma unroll
            for (int j = 0; j < 4; ++j) {
                int rr = j >> 1;
                float pexp = __expf(sf[nf][j] - m[rr]);
                sf[nf][j] = pexp;
                ls[rr] += pexp;
            }
        #pragma unroll
        for (int rr = 0; rr < 2; ++rr) {
            ls[rr] += __shfl_xor_sync(0xffffffffu, ls[rr], 1);
            ls[rr] += __shfl_xor_sync(0xffffffffu, ls[rr], 2);
            l[rr] = l[rr] * alpha[rr] + ls[rr];
        }
        #pragma unroll
        for (int nf = 0; nf < 8; ++nf) {
            o[nf][0] *= alpha[0];
            o[nf][1] *= alpha[0];
            o[nf][2] *= alpha[1];
            o[nf][3] *= alpha[1];
        }

        // --- O += P V : P fragments built in registers ---
        #pragma unroll
        for (int ks = 0; ks < 4; ++ks) {
            uint32_t pa[4];
            pa[0] = pack_h2(sf[2 * ks][0],     sf[2 * ks][1]);
            pa[1] = pack_h2(sf[2 * ks][2],     sf[2 * ks][3]);
            pa[2] = pack_h2(sf[2 * ks + 1][0], sf[2 * ks + 1][1]);
            pa[3] = pack_h2(sf[2 * ks + 1][2], sf[2 * ks + 1][3]);
            #pragma unroll
            for (int nf = 0; nf < 8; ++nf) {
                int hh = nf * 8 + g;
                mma_f16(o[nf], pa,
                        V2[buf][(ks * 8 + tg) * V2_STR + hh],
                        V2[buf][(ks * 8 + tg + 4) * V2_STR + hh]);
            }
        }

        __syncthreads();
    }

    const float inv0 = 1.0f / l[0];
    const float inv1 = 1.0f / l[1];
    const int grow = b * T + qt * 64 + wid * 16 + g;
    #pragma unroll
    for (int nf = 0; nf < 8; ++nf) {
        int col = nf * 8 + 2 * tg;
        *(float2*)&out[grow * H + col] =
            make_float2(o[nf][0] * inv0, o[nf][1] * inv0);
        *(float2*)&out[(grow + 8) * H + col] =
            make_float2(o[nf][2] * inv1, o[nf][3] * inv1);
    }
}

// ---------------------------------------------------------------------------
extern "C" void kernel_launch(void* const* d_in, const int* in_sizes, int n_in,
                              void* d_out, int out_size)
{
    const float* x  = (const float*)d_in[0];
    const float* Wq = (const float*)d_in[1];
    const float* Wk = (const float*)d_in[2];
    const float* Wv = (const float*)d_in[3];
    float* out = (float*)d_out;

    pack_w_kernel<<<144, 256>>>(Wq, Wk, Wv);

    cudaFuncSetAttribute(qkv_proj_kernel,
                         cudaFuncAttributeMaxDynamicSharedMemorySize,
                         QKV_SMEM_BYTES);
    qkv_proj_kernel<<<dim3(3, BT / 128), 256, QKV_SMEM_BYTES>>>(x);

    attn_kernel<<<dim3(BATCH, T / 64), 128>>>(out);
}